// round 1
// baseline (speedup 1.0000x reference)
#include <cuda_runtime.h>
#include <cuda_bf16.h>

// ArcFaceLoss: N=8192 rows, C=32000 classes, fp32 pred, int target.
// loss_i = lse(logits_i) - S*margin(c_t)   where logits = 30*clamp(pred,-1,1)
// with target column replaced by the arcface margin value.
// Key trick: clamp bounds logits to [-30,30] -> fixed softmax max of 30,
// so one streaming pass computes sum(exp(30c-30)); the target column is
// patched afterward as a rank-1 correction (one extra scalar load).

#define N_ROWS 8192
#define C_COLS 32000

__device__ float g_row_loss[N_ROWS];
__device__ int   g_tgt_is64;

// ---- constants ----
// M = 0.5
// MM        = sin(pi-M)*M = sin(0.5)*0.5
// THRESHOLD = cos(pi-M)   = -cos(0.5)
#define COS_M      0.877582561890373f
#define SIN_M      0.479425538604203f
#define MM_CONST   0.239712769302101f
#define THRESH    -0.877582561890373f
#define S_SCALE    30.0f
// K2 = S * log2(e)  so exp(S*c - S) == exp2(K2*c - K2)
#define K2         43.28085122666891f

__device__ __forceinline__ float clamp1(float x) {
    return fminf(fmaxf(x, -1.0f), 1.0f);
}

__device__ __forceinline__ float eterm(float c) {
    // exp(30*c - 30) via exp2
    return exp2f(fmaf(K2, c, -K2));
}

// ---------------------------------------------------------------------------
// Kernel 0: detect whether target buffer is int64 or int32.
// For int64 targets (values < 32000), every high 32-bit word is 0.
// For random int32 targets in [0,32000), 64 consecutive odd words all being
// zero has probability ~(1/32000)^64 ~ 0.
__global__ void detect_tgt_kernel(const int* __restrict__ tgt) {
    if (threadIdx.x == 0) {
        int is64 = 1;
        #pragma unroll 1
        for (int i = 0; i < 64; i++) {
            if (tgt[2 * i + 1] != 0) { is64 = 0; break; }
        }
        g_tgt_is64 = is64;
    }
}

// ---------------------------------------------------------------------------
// Kernel 1: one block per row. 256 threads stream 32000 floats (float4) and
// accumulate sum(exp(30*clamp(x)-30)). Block-reduce, then thread 0 applies the
// target-column margin correction and writes the per-row loss.
__global__ __launch_bounds__(256) void row_loss_kernel(
    const float* __restrict__ pred,
    const void*  __restrict__ tgt)
{
    const int row = blockIdx.x;
    const int tid = threadIdx.x;
    const float4* __restrict__ p =
        reinterpret_cast<const float4*>(pred + (size_t)row * C_COLS);

    // 32000/4 = 8000 float4 per row
    float s0 = 0.0f, s1 = 0.0f;
    #pragma unroll 4
    for (int i = tid; i < C_COLS / 4; i += 256) {
        float4 v = p[i];
        s0 += eterm(clamp1(v.x)) + eterm(clamp1(v.y));
        s1 += eterm(clamp1(v.z)) + eterm(clamp1(v.w));
    }
    float s = s0 + s1;

    // block reduction: warp shuffle + smem
    __shared__ float warp_part[8];
    #pragma unroll
    for (int off = 16; off > 0; off >>= 1)
        s += __shfl_down_sync(0xFFFFFFFFu, s, off);
    if ((tid & 31) == 0) warp_part[tid >> 5] = s;
    __syncthreads();

    if (tid == 0) {
        float total = 0.0f;
        #pragma unroll
        for (int w = 0; w < 8; w++) total += warp_part[w];

        // target index (dtype-robust)
        long long t;
        if (g_tgt_is64) t = reinterpret_cast<const long long*>(tgt)[row];
        else            t = reinterpret_cast<const int*>(tgt)[row];

        float c = clamp1(pred[(size_t)row * C_COLS + t]);

        // arcface margin on the target cosine
        float tm;
        if (c > THRESH) {
            float sn = sqrtf(fmaxf(1.0f - c * c, 0.0f));
            tm = fmaf(c, COS_M, -sn * SIN_M);   // cos(acos(c)+M)
        } else {
            tm = c - MM_CONST;
        }

        // rank-1 correction of the sum: swap original target term for margin term
        float sum = total - eterm(c) + eterm(tm);

        // loss = lse - S*tm = (S + log(sum)) - S*tm
        g_row_loss[row] = S_SCALE + logf(sum) - S_SCALE * tm;
    }
}

// ---------------------------------------------------------------------------
// Kernel 2: mean of the 8192 row losses -> d_out[0]
__global__ __launch_bounds__(1024) void reduce_kernel(float* __restrict__ out) {
    const int tid = threadIdx.x;
    float s = 0.0f;
    #pragma unroll
    for (int i = tid; i < N_ROWS; i += 1024) s = s + g_row_loss[i];

    __shared__ float warp_part[32];
    #pragma unroll
    for (int off = 16; off > 0; off >>= 1)
        s += __shfl_down_sync(0xFFFFFFFFu, s, off);
    if ((tid & 31) == 0) warp_part[tid >> 5] = s;
    __syncthreads();

    if (tid < 32) {
        float v = warp_part[tid];
        #pragma unroll
        for (int off = 16; off > 0; off >>= 1)
            v += __shfl_down_sync(0xFFFFFFFFu, v, off);
        if (tid == 0) out[0] = v * (1.0f / (float)N_ROWS);
    }
}

// ---------------------------------------------------------------------------
extern "C" void kernel_launch(void* const* d_in, const int* in_sizes, int n_in,
                              void* d_out, int out_size)
{
    const float* pred = (const float*)d_in[0];
    const void*  tgt  = d_in[1];
    float* out = (float*)d_out;

    detect_tgt_kernel<<<1, 32>>>((const int*)tgt);
    row_loss_kernel<<<N_ROWS, 256>>>(pred, tgt);
    reduce_kernel<<<1, 1024>>>(out);
}